// round 1
// baseline (speedup 1.0000x reference)
#include <cuda_runtime.h>
#include <cstdint>
#include <cstdio>

// Problem constants (fixed by the reference setup)
#define BB   2
#define LL   2048
#define DM   1024
#define DIN  2048
#define NST  16
#define DTR  64
#define ROWS (BB * LL)   // 4096
#define DBC_COLS 96      // dt_rank(64) + N(16) + N(16)

// ---------------------------------------------------------------------------
// Scratch (static device globals — no allocation allowed)
// ---------------------------------------------------------------------------
__device__ float g_xn[(size_t)ROWS * DM];          // 16 MB  layernorm output
__device__ float g_xz[(size_t)ROWS * 2 * DIN];     // 64 MB  in_proj output (u | z)
__device__ float g_u[(size_t)ROWS * DIN];          // 32 MB  silu(conv(u))
__device__ float g_dbc[(size_t)ROWS * DBC_COLS];   // 1.5 MB dt | B | C
__device__ float g_delta[(size_t)ROWS * DIN];      // 32 MB  softplus(dt@W + b)
__device__ float g_yg[(size_t)ROWS * DIN];         // 32 MB  scan output * silu(z)

// ---------------------------------------------------------------------------
// f32x2 packed FMA helpers (full-rate fp32 on Blackwell; 3-reg FFMA is half rate)
// ---------------------------------------------------------------------------
__device__ __forceinline__ unsigned long long pack_dup(float a) {
    unsigned long long r;
    asm("mov.b64 %0, {%1, %1};" : "=l"(r) : "f"(a));
    return r;
}
__device__ __forceinline__ void ffma2(unsigned long long& d,
                                      unsigned long long a,
                                      unsigned long long b) {
    asm("fma.rn.f32x2 %0, %1, %2, %0;" : "+l"(d) : "l"(a), "l"(b));
}

// ---------------------------------------------------------------------------
// LayerNorm: one block per row (1024 elems), 256 threads, float4 I/O
// ---------------------------------------------------------------------------
__global__ void ln_kernel(const float* __restrict__ x,
                          const float* __restrict__ g,
                          const float* __restrict__ b) {
    const int row = blockIdx.x;
    const int tid = threadIdx.x;   // 0..255
    const float4 v = reinterpret_cast<const float4*>(x + (size_t)row * DM)[tid];
    float s = v.x + v.y + v.z + v.w;
    float q = v.x * v.x + v.y * v.y + v.z * v.z + v.w * v.w;
#pragma unroll
    for (int o = 16; o > 0; o >>= 1) {
        s += __shfl_xor_sync(0xffffffffu, s, o);
        q += __shfl_xor_sync(0xffffffffu, q, o);
    }
    __shared__ float rs[8], rq[8];
    if ((tid & 31) == 0) { rs[tid >> 5] = s; rq[tid >> 5] = q; }
    __syncthreads();
    s = 0.f; q = 0.f;
#pragma unroll
    for (int i = 0; i < 8; i++) { s += rs[i]; q += rq[i]; }
    const float mean = s * (1.f / DM);
    const float var  = q * (1.f / DM) - mean * mean;
    const float rstd = rsqrtf(var + 1e-5f);
    const float4 gv = reinterpret_cast<const float4*>(g)[tid];
    const float4 bv = reinterpret_cast<const float4*>(b)[tid];
    float4 o;
    o.x = (v.x - mean) * rstd * gv.x + bv.x;
    o.y = (v.y - mean) * rstd * gv.y + bv.y;
    o.z = (v.z - mean) * rstd * gv.z + bv.z;
    o.w = (v.w - mean) * rstd * gv.w + bv.w;
    reinterpret_cast<float4*>(g_xn + (size_t)row * DM)[tid] = o;
}

// ---------------------------------------------------------------------------
// Generic fp32 SGEMM: C[M,N] = A[M,K] @ B[K,N]
// 128x128 tiles, BK=8, 256 threads, 8x8 microtile, f32x2 inner loop.
// EPI: 0 = none, 1 = softplus(acc + bias[col]), 2 = acc + residual[row,col]
// SPLITK: partial-K accumulation via atomicAdd (C must be pre-zeroed)
// Assumes M % 128 == 0 and K % 8 == 0 (true for all call sites).
// ---------------------------------------------------------------------------
template <int EPI, bool GUARD_N, bool SPLITK>
__global__ void __launch_bounds__(256, 2)
sgemm_kernel(const float* __restrict__ A, const float* __restrict__ B,
             float* __restrict__ C, int M, int N, int K,
             int lda, int ldb, int ldc, const float* __restrict__ aux) {
    __shared__ float As[8][132];
    __shared__ float Bs[8][132];

    const int tid = threadIdx.x;
    const int tx = tid & 15, ty = tid >> 4;
    const int rowBase = blockIdx.y * 128;
    const int colBase = blockIdx.x * 128;
    const int ar = tid >> 1, ak = (tid & 1) * 4;   // A tile: 128 rows x 8 k
    const int br = tid >> 5, bc = (tid & 31) * 4;  // B tile: 8 k x 128 cols

    int k0 = 0, kEnd = K;
    if (SPLITK) {
        const int chunk = K / gridDim.z;
        k0 = blockIdx.z * chunk;
        kEnd = k0 + chunk;
    }

    union AccU { float f[8][8]; unsigned long long u[8][4]; } acc;
#pragma unroll
    for (int i = 0; i < 8; i++)
#pragma unroll
        for (int j = 0; j < 4; j++) acc.u[i][j] = 0ULL;

    for (; k0 < kEnd; k0 += 8) {
        const float4 av = *reinterpret_cast<const float4*>(
            &A[(size_t)(rowBase + ar) * lda + k0 + ak]);
        As[ak + 0][ar] = av.x;
        As[ak + 1][ar] = av.y;
        As[ak + 2][ar] = av.z;
        As[ak + 3][ar] = av.w;

        float4 bv = make_float4(0.f, 0.f, 0.f, 0.f);
        if (!GUARD_N || (colBase + bc) < N)
            bv = *reinterpret_cast<const float4*>(
                &B[(size_t)(k0 + br) * ldb + colBase + bc]);
        *reinterpret_cast<float4*>(&Bs[br][bc]) = bv;
        __syncthreads();

#pragma unroll
        for (int kk = 0; kk < 8; kk++) {
            float afr[8];
            union { float f[8]; unsigned long long u[4]; } bfr;
            *reinterpret_cast<float4*>(&afr[0]) =
                *reinterpret_cast<const float4*>(&As[kk][ty * 8]);
            *reinterpret_cast<float4*>(&afr[4]) =
                *reinterpret_cast<const float4*>(&As[kk][ty * 8 + 4]);
            *reinterpret_cast<float4*>(&bfr.f[0]) =
                *reinterpret_cast<const float4*>(&Bs[kk][tx * 8]);
            *reinterpret_cast<float4*>(&bfr.f[4]) =
                *reinterpret_cast<const float4*>(&Bs[kk][tx * 8 + 4]);
#pragma unroll
            for (int i = 0; i < 8; i++) {
                const unsigned long long ap = pack_dup(afr[i]);
#pragma unroll
                for (int j = 0; j < 4; j++) ffma2(acc.u[i][j], ap, bfr.u[j]);
            }
        }
        __syncthreads();
    }

#pragma unroll
    for (int i = 0; i < 8; i++) {
        const int row = rowBase + ty * 8 + i;
#pragma unroll
        for (int j = 0; j < 8; j++) {
            const int col = colBase + tx * 8 + j;
            if (GUARD_N && col >= N) continue;
            float v = acc.f[i][j];
            if (SPLITK) {
                atomicAdd(&C[(size_t)row * ldc + col], v);
            } else {
                if (EPI == 1) {
                    v += aux[col];
                    v = (v > 20.f) ? v : log1pf(__expf(v));
                } else if (EPI == 2) {
                    v += aux[(size_t)row * ldc + col];
                }
                C[(size_t)row * ldc + col] = v;
            }
        }
    }
}

// ---------------------------------------------------------------------------
// Depthwise causal conv (k=4) over the u-half of xz, + bias + SiLU
// ---------------------------------------------------------------------------
__global__ void conv_silu_kernel(const float* __restrict__ cw,
                                 const float* __restrict__ cb) {
    const int idx = blockIdx.x * blockDim.x + threadIdx.x;  // ROWS*DIN
    const int d = idx & (DIN - 1);
    const int row = idx >> 11;          // DIN = 2048
    const int l = row & (LL - 1);
    const int b = row >> 11;            // LL = 2048
    const float* base = g_xz + (size_t)(b * LL) * (2 * DIN) + d;

    float acc = cb[d];
    if (l >= 3) {
        acc += cw[d * 4 + 0] * base[(size_t)(l - 3) * (2 * DIN)]
             + cw[d * 4 + 1] * base[(size_t)(l - 2) * (2 * DIN)]
             + cw[d * 4 + 2] * base[(size_t)(l - 1) * (2 * DIN)]
             + cw[d * 4 + 3] * base[(size_t)(l    ) * (2 * DIN)];
    } else {
#pragma unroll
        for (int j = 0; j < 4; j++) {
            const int ll = l + j - 3;
            if (ll >= 0) acc += cw[d * 4 + j] * base[(size_t)ll * (2 * DIN)];
        }
    }
    acc = acc / (1.f + __expf(-acc));   // SiLU
    g_u[(size_t)row * DIN + d] = acc;
}

__global__ void zero_kernel(float* __restrict__ p, int n) {
    const int i = blockIdx.x * blockDim.x + threadIdx.x;
    if (i < n) p[i] = 0.f;
}

// ---------------------------------------------------------------------------
// Selective scan. One channel (b,d) per 16 lanes; lane = state index n.
// Fuses y = (scan + u*D) * silu(z) into the epilogue.
// ---------------------------------------------------------------------------
__global__ void scan_kernel(const float* __restrict__ A_log,
                            const float* __restrict__ Dv) {
    const int c = blockIdx.x * (blockDim.x >> 4) + (threadIdx.x >> 4);
    const int n = threadIdx.x & 15;
    const int b = c >> 11;              // DIN = 2048 channels per batch
    const int d = c & (DIN - 1);

    const float An = -__expf(A_log[d * NST + n]);
    const float Dd = Dv[d];
    float h = 0.f;
    const size_t rowStart = (size_t)b * LL;

    for (int l = 0; l < LL; ++l) {
        const size_t row = rowStart + l;
        const float dv = g_delta[row * DIN + d];
        const float uv = g_u[row * DIN + d];
        const float Bn = g_dbc[row * DBC_COLS + DTR + n];
        const float Cn = g_dbc[row * DBC_COLS + DTR + NST + n];
        const float dA = __expf(dv * An);
        h = fmaf(dA, h, dv * Bn * uv);
        float p = h * Cn;
        p += __shfl_xor_sync(0xffffffffu, p, 8);
        p += __shfl_xor_sync(0xffffffffu, p, 4);
        p += __shfl_xor_sync(0xffffffffu, p, 2);
        p += __shfl_xor_sync(0xffffffffu, p, 1);
        if (n == 0) {
            const float zv = g_xz[row * (2 * DIN) + DIN + d];
            const float yv = fmaf(uv, Dd, p);
            const float sz = zv / (1.f + __expf(-zv));
            g_yg[row * DIN + d] = yv * sz;
        }
    }
}

// ---------------------------------------------------------------------------
// Launch
// ---------------------------------------------------------------------------
extern "C" void kernel_launch(void* const* d_in, const int* in_sizes, int n_in,
                              void* d_out, int out_size) {
    (void)in_sizes; (void)n_in; (void)out_size;
    const float* x         = (const float*)d_in[0];
    const float* in_proj_w = (const float*)d_in[1];
    const float* conv_w    = (const float*)d_in[2];
    const float* conv_b    = (const float*)d_in[3];
    const float* x_proj_w  = (const float*)d_in[4];
    const float* dt_proj_w = (const float*)d_in[5];
    const float* dt_proj_b = (const float*)d_in[6];
    const float* A_log     = (const float*)d_in[7];
    const float* Dvec      = (const float*)d_in[8];
    const float* out_proj_w= (const float*)d_in[9];
    const float* ln_g      = (const float*)d_in[10];
    const float* ln_b      = (const float*)d_in[11];
    float* out = (float*)d_out;

    float *xn, *xz, *u, *dbc, *delta, *yg;
    cudaGetSymbolAddress((void**)&xn,    g_xn);
    cudaGetSymbolAddress((void**)&xz,    g_xz);
    cudaGetSymbolAddress((void**)&u,     g_u);
    cudaGetSymbolAddress((void**)&dbc,   g_dbc);
    cudaGetSymbolAddress((void**)&delta, g_delta);
    cudaGetSymbolAddress((void**)&yg,    g_yg);

    // 1. LayerNorm
    ln_kernel<<<ROWS, 256>>>(x, ln_g, ln_b);

    // 2. in_proj: xz[4096,4096] = xn[4096,1024] @ W[1024,4096]
    sgemm_kernel<0, false, false><<<dim3(32, 32), 256>>>(
        xn, in_proj_w, xz, ROWS, 2 * DIN, DM, DM, 2 * DIN, 2 * DIN, nullptr);

    // 3. causal depthwise conv + SiLU -> u
    conv_silu_kernel<<<(ROWS * DIN) / 256, 256>>>(conv_w, conv_b);

    // 4. x_proj: dbc[4096,96] = u @ W[2048,96]   (split-K=8, atomic accumulate)
    zero_kernel<<<(ROWS * DBC_COLS) / 256, 256>>>(dbc, ROWS * DBC_COLS);
    sgemm_kernel<0, true, true><<<dim3(1, 32, 8), 256>>>(
        u, x_proj_w, dbc, ROWS, DBC_COLS, DIN, DIN, DBC_COLS, DBC_COLS, nullptr);

    // 5. dt_proj + softplus: delta[4096,2048] = softplus(dt[4096,64]@W + b)
    sgemm_kernel<1, false, false><<<dim3(16, 32), 256>>>(
        dbc, dt_proj_w, delta, ROWS, DIN, DTR, DBC_COLS, DIN, DIN, dt_proj_b);

    // 6. selective scan + D skip + silu(z) gate -> yg
    scan_kernel<<<(BB * DIN) / 8, 128>>>(A_log, Dvec);

    // 7. out_proj + residual: out = x + yg @ W[2048,1024]
    sgemm_kernel<2, false, false><<<dim3(8, 32), 256>>>(
        yg, out_proj_w, out, ROWS, DM, DIN, DIN, DM, DM, x);
}

// round 4
// speedup vs baseline: 1.2768x; 1.2768x over previous
#include <cuda_runtime.h>
#include <cstdint>
#include <cstdio>

// Problem constants
#define BB   2
#define LL   2048
#define DM   1024
#define DIN  2048
#define NST  16
#define DTR  64
#define ROWS (BB * LL)   // 4096
#define DBC_COLS 96

// ---------------------------------------------------------------------------
// Scratch (static device globals — no allocation allowed)
// ---------------------------------------------------------------------------
__device__ float g_xn[(size_t)ROWS * DM];           // LN out (tf32-rounded)
__device__ float g_xz[(size_t)ROWS * 2 * DIN];      // in_proj out (u | z)
__device__ float g_u[(size_t)ROWS * DIN];           // silu(conv(u))
__device__ float g_dbc[(size_t)ROWS * DBC_COLS];    // dt | B | C
__device__ float g_delta[(size_t)ROWS * DIN];       // softplus(dt@W + b)
__device__ float g_yg[(size_t)ROWS * DIN];          // gated scan out (tf32-rounded)
__device__ float g_w1[(size_t)DM * 2 * DIN];        // in_proj_w  tf32-rounded
__device__ float g_w2[(size_t)DIN * DM];            // out_proj_w tf32-rounded

// ---------------------------------------------------------------------------
// helpers
// ---------------------------------------------------------------------------
__device__ __forceinline__ float round_tf32(float v) {
    uint32_t r;
    asm("cvt.rna.tf32.f32 %0, %1;" : "=r"(r) : "f"(v));
    return __uint_as_float(r);
}
__device__ __forceinline__ void cpa16(float* smem_dst, const float* g) {
    uint32_t s;
    asm("{ .reg .u64 t; cvta.to.shared.u64 t, %1; cvt.u32.u64 %0, t; }"
        : "=r"(s) : "l"(smem_dst));
    asm volatile("cp.async.cg.shared.global [%0], [%1], 16;" :: "r"(s), "l"(g));
}
__device__ __forceinline__ void mma_tf32(float* c, const uint32_t* a,
                                         const uint32_t* b) {
    asm volatile(
        "mma.sync.aligned.m16n8k8.row.col.f32.tf32.tf32.f32 "
        "{%0,%1,%2,%3}, {%4,%5,%6,%7}, {%8,%9}, {%0,%1,%2,%3};"
        : "+f"(c[0]), "+f"(c[1]), "+f"(c[2]), "+f"(c[3])
        : "r"(a[0]), "r"(a[1]), "r"(a[2]), "r"(a[3]), "r"(b[0]), "r"(b[1]));
}

// ---------------------------------------------------------------------------
// tf32 tensor-core GEMM: C[M,N] = A[M,K] @ B[K,N]   (both row-major fp32,
// values pre-rounded to tf32). CTA tile 128x128, BK=32, double-buffered
// cp.async. 8 warps in 2(m) x 4(n); warp tile 64x32; m16n8k8 HMMA.
// ---------------------------------------------------------------------------
#define AS_STRIDE 36
#define BS_STRIDE 132
#define AS_FLOATS (128 * AS_STRIDE)             // 4608
#define BS_FLOATS (32 * BS_STRIDE)              // 4224
#define STAGE_FLOATS (AS_FLOATS + BS_FLOATS)    // 8832
#define GEMM_SMEM_BYTES (2 * STAGE_FLOATS * 4)  // 70656

template <bool RESID>
__global__ void __launch_bounds__(256, 1)
mma_gemm(const float* __restrict__ A, const float* __restrict__ B,
         float* __restrict__ C, const float* __restrict__ resid,
         int K, int N, int ldc) {
    extern __shared__ float sm[];
    const int tid = threadIdx.x;
    const int lane = tid & 31, wid = tid >> 5;
    const int wm = (wid & 1) * 64;        // warp m offset in tile
    const int wn = (wid >> 1) * 32;       // warp n offset in tile
    const int m0 = blockIdx.y * 128;
    const int n0 = blockIdx.x * 128;
    const int g = lane >> 2, tk = lane & 3;

    float acc[4][4][4];
#pragma unroll
    for (int i = 0; i < 4; i++)
#pragma unroll
        for (int j = 0; j < 4; j++)
#pragma unroll
            for (int l = 0; l < 4; l++) acc[i][j][l] = 0.f;

    const int nCh = K >> 5;

    // ---- stage loader ----
    auto load_stage = [&](int ch, int s) {
        float* As = sm + s * STAGE_FLOATS;
        float* Bs = As + AS_FLOATS;
        const int k0 = ch * 32;
#pragma unroll
        for (int i = 0; i < 4; i++) {
            const int t = tid + i * 256;
            const int row = t >> 3, kq = (t & 7) * 4;
            cpa16(&As[row * AS_STRIDE + kq], &A[(size_t)(m0 + row) * K + k0 + kq]);
        }
#pragma unroll
        for (int i = 0; i < 4; i++) {
            const int t = tid + i * 256;
            const int kr = t >> 5, nq = (t & 31) * 4;
            cpa16(&Bs[kr * BS_STRIDE + nq], &B[(size_t)(k0 + kr) * N + n0 + nq]);
        }
        asm volatile("cp.async.commit_group;");
    };

    load_stage(0, 0);

#pragma unroll 1
    for (int ch = 0; ch < nCh; ch++) {
        const int s = ch & 1;
        if (ch + 1 < nCh) {
            load_stage(ch + 1, s ^ 1);
            asm volatile("cp.async.wait_group 1;" ::: "memory");
        } else {
            asm volatile("cp.async.wait_group 0;" ::: "memory");
        }
        __syncthreads();

        const uint32_t* Asu = reinterpret_cast<const uint32_t*>(sm + s * STAGE_FLOATS);
        const uint32_t* Bsu = Asu + AS_FLOATS;
#pragma unroll
        for (int kk = 0; kk < 32; kk += 8) {
            uint32_t bfr[4][2];
#pragma unroll
            for (int nt = 0; nt < 4; nt++) {
                const int col = wn + nt * 8 + g;
                bfr[nt][0] = Bsu[(kk + tk) * BS_STRIDE + col];
                bfr[nt][1] = Bsu[(kk + tk + 4) * BS_STRIDE + col];
            }
            uint32_t afr[4][4];
#pragma unroll
            for (int mt = 0; mt < 4; mt++) {
                const int base = (wm + mt * 16 + g) * AS_STRIDE + kk + tk;
                afr[mt][0] = Asu[base];
                afr[mt][1] = Asu[base + 8 * AS_STRIDE];
                afr[mt][2] = Asu[base + 4];
                afr[mt][3] = Asu[base + 8 * AS_STRIDE + 4];
            }
#pragma unroll
            for (int mt = 0; mt < 4; mt++)
#pragma unroll
                for (int nt = 0; nt < 4; nt++)
                    mma_tf32(acc[mt][nt], afr[mt], bfr[nt]);
        }
        __syncthreads();
    }

    // ---- epilogue: direct fragment stores (float2, 32B sectors) ----
#pragma unroll
    for (int mt = 0; mt < 4; mt++) {
        const int row = m0 + wm + mt * 16 + g;
#pragma unroll
        for (int nt = 0; nt < 4; nt++) {
            const int col = n0 + wn + nt * 8 + tk * 2;
            float2 v0 = make_float2(acc[mt][nt][0], acc[mt][nt][1]);
            float2 v1 = make_float2(acc[mt][nt][2], acc[mt][nt][3]);
            const size_t o0 = (size_t)row * ldc + col;
            const size_t o1 = (size_t)(row + 8) * ldc + col;
            if (RESID) {
                const float2 r0 = *reinterpret_cast<const float2*>(&resid[o0]);
                const float2 r1 = *reinterpret_cast<const float2*>(&resid[o1]);
                v0.x += r0.x; v0.y += r0.y;
                v1.x += r1.x; v1.y += r1.y;
            }
            *reinterpret_cast<float2*>(&C[o0]) = v0;
            *reinterpret_cast<float2*>(&C[o1]) = v1;
        }
    }
}

// ---------------------------------------------------------------------------
// LayerNorm -> tf32-rounded fp32
// ---------------------------------------------------------------------------
__global__ void ln_kernel(const float* __restrict__ x,
                          const float* __restrict__ g,
                          const float* __restrict__ b) {
    const int row = blockIdx.x;
    const int tid = threadIdx.x;
    const float4 v = reinterpret_cast<const float4*>(x + (size_t)row * DM)[tid];
    float s = v.x + v.y + v.z + v.w;
    float q = v.x * v.x + v.y * v.y + v.z * v.z + v.w * v.w;
#pragma unroll
    for (int o = 16; o > 0; o >>= 1) {
        s += __shfl_xor_sync(0xffffffffu, s, o);
        q += __shfl_xor_sync(0xffffffffu, q, o);
    }
    __shared__ float rs[8], rq[8];
    if ((tid & 31) == 0) { rs[tid >> 5] = s; rq[tid >> 5] = q; }
    __syncthreads();
    s = 0.f; q = 0.f;
#pragma unroll
    for (int i = 0; i < 8; i++) { s += rs[i]; q += rq[i]; }
    const float mean = s * (1.f / DM);
    const float var  = q * (1.f / DM) - mean * mean;
    const float rstd = rsqrtf(var + 1e-5f);
    const float4 gv = reinterpret_cast<const float4*>(g)[tid];
    const float4 bv = reinterpret_cast<const float4*>(b)[tid];
    float4 o;
    o.x = round_tf32((v.x - mean) * rstd * gv.x + bv.x);
    o.y = round_tf32((v.y - mean) * rstd * gv.y + bv.y);
    o.z = round_tf32((v.z - mean) * rstd * gv.z + bv.z);
    o.w = round_tf32((v.w - mean) * rstd * gv.w + bv.w);
    reinterpret_cast<float4*>(g_xn + (size_t)row * DM)[tid] = o;
}

// ---------------------------------------------------------------------------
// Elementwise tf32 rounding (weight prep)
// ---------------------------------------------------------------------------
__global__ void round_kernel(const float* __restrict__ in, float* __restrict__ out,
                             int n4) {
    const int i = blockIdx.x * 256 + threadIdx.x;
    if (i >= n4) return;
    float4 v = reinterpret_cast<const float4*>(in)[i];
    v.x = round_tf32(v.x); v.y = round_tf32(v.y);
    v.z = round_tf32(v.z); v.w = round_tf32(v.w);
    reinterpret_cast<float4*>(out)[i] = v;
}

// ---------------------------------------------------------------------------
// SIMT fp32 GEMM (f32x2) for small projections
// ---------------------------------------------------------------------------
__device__ __forceinline__ unsigned long long pack_dup(float a) {
    unsigned long long r;
    asm("mov.b64 %0, {%1, %1};" : "=l"(r) : "f"(a));
    return r;
}
__device__ __forceinline__ void ffma2(unsigned long long& d,
                                      unsigned long long a,
                                      unsigned long long b) {
    asm("fma.rn.f32x2 %0, %1, %2, %0;" : "+l"(d) : "l"(a), "l"(b));
}

template <int EPI, bool GUARD_N, bool SPLITK>
__global__ void __launch_bounds__(256, 2)
sgemm_kernel(const float* __restrict__ A, const float* __restrict__ B,
             float* __restrict__ C, int M, int N, int K,
             int lda, int ldb, int ldc, const float* __restrict__ aux) {
    __shared__ float As[8][132];
    __shared__ float Bs[8][132];
    const int tid = threadIdx.x;
    const int tx = tid & 15, ty = tid >> 4;
    const int rowBase = blockIdx.y * 128;
    const int colBase = blockIdx.x * 128;
    const int ar = tid >> 1, ak = (tid & 1) * 4;
    const int br = tid >> 5, bc = (tid & 31) * 4;

    int k0 = 0, kEnd = K;
    if (SPLITK) {
        const int chunk = K / gridDim.z;
        k0 = blockIdx.z * chunk;
        kEnd = k0 + chunk;
    }
    union AccU { float f[8][8]; unsigned long long u[8][4]; } acc;
#pragma unroll
    for (int i = 0; i < 8; i++)
#pragma unroll
        for (int j = 0; j < 4; j++) acc.u[i][j] = 0ULL;

    for (; k0 < kEnd; k0 += 8) {
        const float4 av = *reinterpret_cast<const float4*>(
            &A[(size_t)(rowBase + ar) * lda + k0 + ak]);
        As[ak + 0][ar] = av.x; As[ak + 1][ar] = av.y;
        As[ak + 2][ar] = av.z; As[ak + 3][ar] = av.w;
        float4 bv = make_float4(0.f, 0.f, 0.f, 0.f);
        if (!GUARD_N || (colBase + bc) < N)
            bv = *reinterpret_cast<const float4*>(
                &B[(size_t)(k0 + br) * ldb + colBase + bc]);
        *reinterpret_cast<float4*>(&Bs[br][bc]) = bv;
        __syncthreads();
#pragma unroll
        for (int kk = 0; kk < 8; kk++) {
            float afr[8];
            union { float f[8]; unsigned long long u[4]; } bfr;
            *reinterpret_cast<float4*>(&afr[0]) =
                *reinterpret_cast<const float4*>(&As[kk][ty * 8]);
            *reinterpret_cast<float4*>(&afr[4]) =
                *reinterpret_cast<const float4*>(&As[kk][ty * 8 + 4]);
            *reinterpret_cast<float4*>(&bfr.f[0]) =
                *reinterpret_cast<const float4*>(&Bs[kk][tx * 8]);
            *reinterpret_cast<float4*>(&bfr.f[4]) =
                *reinterpret_cast<const float4*>(&Bs[kk][tx * 8 + 4]);
#pragma unroll
            for (int i = 0; i < 8; i++) {
                const unsigned long long ap = pack_dup(afr[i]);
#pragma unroll
                for (int j = 0; j < 4; j++) ffma2(acc.u[i][j], ap, bfr.u[j]);
            }
        }
        __syncthreads();
    }
#pragma unroll
    for (int i = 0; i < 8; i++) {
        const int row = rowBase + ty * 8 + i;
#pragma unroll
        for (int j = 0; j < 8; j++) {
            const int col = colBase + tx * 8 + j;
            if (GUARD_N && col >= N) continue;
            float v = acc.f[i][j];
            if (SPLITK) {
                atomicAdd(&C[(size_t)row * ldc + col], v);
            } else {
                if (EPI == 1) {
                    v += aux[col];
                    v = (v > 20.f) ? v : log1pf(__expf(v));
                }
                C[(size_t)row * ldc + col] = v;
            }
        }
    }
}

// ---------------------------------------------------------------------------
// Depthwise causal conv (k=4) + bias + SiLU
// ---------------------------------------------------------------------------
__global__ void conv_silu_kernel(const float* __restrict__ cw,
                                 const float* __restrict__ cb) {
    const int idx = blockIdx.x * blockDim.x + threadIdx.x;
    const int d = idx & (DIN - 1);
    const int row = idx >> 11;
    const int l = row & (LL - 1);
    const int b = row >> 11;
    const float* base = g_xz + (size_t)(b * LL) * (2 * DIN) + d;
    float acc = cb[d];
    if (l >= 3) {
        acc += cw[d * 4 + 0] * base[(size_t)(l - 3) * (2 * DIN)]
             + cw[d * 4 + 1] * base[(size_t)(l - 2) * (2 * DIN)]
             + cw[d * 4 + 2] * base[(size_t)(l - 1) * (2 * DIN)]
             + cw[d * 4 + 3] * base[(size_t)(l    ) * (2 * DIN)];
    } else {
#pragma unroll
        for (int j = 0; j < 4; j++) {
            const int ll2 = l + j - 3;
            if (ll2 >= 0) acc += cw[d * 4 + j] * base[(size_t)ll2 * (2 * DIN)];
        }
    }
    acc = acc / (1.f + __expf(-acc));
    g_u[(size_t)row * DIN + d] = acc;
}

__global__ void zero_kernel(float* __restrict__ p, int n) {
    const int i = blockIdx.x * blockDim.x + threadIdx.x;
    if (i < n) p[i] = 0.f;
}

// ---------------------------------------------------------------------------
// Selective scan + D skip + silu(z) gate -> yg (tf32-rounded fp32)
// ---------------------------------------------------------------------------
__global__ void scan_kernel(const float* __restrict__ A_log,
                            const float* __restrict__ Dv) {
    const int c = blockIdx.x * (blockDim.x >> 4) + (threadIdx.x >> 4);
    const int n = threadIdx.x & 15;
    const int b = c >> 11;
    const int d = c & (DIN - 1);
    const float An = -__expf(A_log[d * NST + n]);
    const float Dd = Dv[d];
    float h = 0.f;
    const size_t rowStart = (size_t)b * LL;
    for (int l = 0; l < LL; ++l) {
        const size_t row = rowStart + l;
        const float dv = g_delta[row * DIN + d];
        const float uv = g_u[row * DIN + d];
        const float Bn = g_dbc[row * DBC_COLS + DTR + n];
        const float Cn = g_dbc[row * DBC_COLS + DTR + NST + n];
        const float dA = __expf(dv * An);
        h = fmaf(dA, h, dv * Bn * uv);
        float p = h * Cn;
        p += __shfl_xor_sync(0xffffffffu, p, 8);
        p += __shfl_xor_sync(0xffffffffu, p, 4);
        p += __shfl_xor_sync(0xffffffffu, p, 2);
        p += __shfl_xor_sync(0xffffffffu, p, 1);
        if (n == 0) {
            const float zv = g_xz[row * (2 * DIN) + DIN + d];
            const float yv = fmaf(uv, Dd, p);
            const float sz = zv / (1.f + __expf(-zv));
            g_yg[row * DIN + d] = round_tf32(yv * sz);
        }
    }
}

// ---------------------------------------------------------------------------
// Launch
// ---------------------------------------------------------------------------
extern "C" void kernel_launch(void* const* d_in, const int* in_sizes, int n_in,
                              void* d_out, int out_size) {
    (void)in_sizes; (void)n_in; (void)out_size;
    const float* x         = (const float*)d_in[0];
    const float* in_proj_w = (const float*)d_in[1];
    const float* conv_w    = (const float*)d_in[2];
    const float* conv_b    = (const float*)d_in[3];
    const float* x_proj_w  = (const float*)d_in[4];
    const float* dt_proj_w = (const float*)d_in[5];
    const float* dt_proj_b = (const float*)d_in[6];
    const float* A_log     = (const float*)d_in[7];
    const float* Dvec      = (const float*)d_in[8];
    const float* out_proj_w= (const float*)d_in[9];
    const float* ln_g      = (const float*)d_in[10];
    const float* ln_b      = (const float*)d_in[11];
    float* out = (float*)d_out;

    float *xn, *xz, *u, *dbc, *delta, *yg, *w1, *w2;
    cudaGetSymbolAddress((void**)&xn,    g_xn);
    cudaGetSymbolAddress((void**)&xz,    g_xz);
    cudaGetSymbolAddress((void**)&u,     g_u);
    cudaGetSymbolAddress((void**)&dbc,   g_dbc);
    cudaGetSymbolAddress((void**)&delta, g_delta);
    cudaGetSymbolAddress((void**)&yg,    g_yg);
    cudaGetSymbolAddress((void**)&w1,    g_w1);
    cudaGetSymbolAddress((void**)&w2,    g_w2);

    cudaFuncSetAttribute(mma_gemm<false>,
                         cudaFuncAttributeMaxDynamicSharedMemorySize, GEMM_SMEM_BYTES);
    cudaFuncSetAttribute(mma_gemm<true>,
                         cudaFuncAttributeMaxDynamicSharedMemorySize, GEMM_SMEM_BYTES);

    // weight prep: tf32-round
    round_kernel<<<(DM * 2 * DIN / 4 + 255) / 256, 256>>>(in_proj_w, w1, DM * 2 * DIN / 4);
    round_kernel<<<(DIN * DM / 4 + 255) / 256, 256>>>(out_proj_w, w2, DIN * DM / 4);

    // 1. LayerNorm -> tf32-rounded
    ln_kernel<<<ROWS, 256>>>(x, ln_g, ln_b);

    // 2. in_proj (HMMA tf32): xz[4096,4096] = xn[4096,1024] @ W1[1024,4096]
    mma_gemm<false><<<dim3((2 * DIN) / 128, ROWS / 128), 256, GEMM_SMEM_BYTES>>>(
        xn, w1, xz, nullptr, DM, 2 * DIN, 2 * DIN);

    // 3. conv + SiLU -> u
    conv_silu_kernel<<<(ROWS * DIN) / 256, 256>>>(conv_w, conv_b);

    // 4. x_proj (SIMT split-K)
    zero_kernel<<<(ROWS * DBC_COLS) / 256, 256>>>(dbc, ROWS * DBC_COLS);
    sgemm_kernel<0, true, true><<<dim3(1, 32, 8), 256>>>(
        u, x_proj_w, dbc, ROWS, DBC_COLS, DIN, DIN, DBC_COLS, DBC_COLS, nullptr);

    // 5. dt_proj + softplus (SIMT)
    sgemm_kernel<1, false, false><<<dim3(16, 32), 256>>>(
        dbc, dt_proj_w, delta, ROWS, DIN, DTR, DBC_COLS, DIN, DIN, dt_proj_b);

    // 6. scan -> yg (tf32-rounded)
    scan_kernel<<<(BB * DIN) / 8, 128>>>(A_log, Dvec);

    // 7. out_proj (HMMA tf32) + residual: out = x + yg[4096,2048] @ W2[2048,1024]
    mma_gemm<true><<<dim3(DM / 128, ROWS / 128), 256, GEMM_SMEM_BYTES>>>(
        yg, w2, out, x, DIN, DM, DM);
}

// round 6
// speedup vs baseline: 2.4496x; 1.9185x over previous
#include <cuda_runtime.h>
#include <cstdint>
#include <cstdio>

// Problem constants
#define BB   2
#define LL   2048
#define DM   1024
#define DIN  2048
#define NST  16
#define DTR  64
#define ROWS (BB * LL)   // 4096
#define DBC_COLS 96
#define CHUNK  64
#define NCHUNK 32        // LL / CHUNK

// ---------------------------------------------------------------------------
// Scratch (static device globals — no allocation allowed)
// ---------------------------------------------------------------------------
__device__ float g_xn[(size_t)ROWS * DM];           // LN out (tf32-rounded)
__device__ float g_xz[(size_t)ROWS * 2 * DIN];      // in_proj out (u | z)
__device__ float g_u[(size_t)ROWS * DIN];           // silu(conv(u))
__device__ float g_dbc[(size_t)ROWS * DBC_COLS];    // dt | B | C
__device__ float g_delta[(size_t)ROWS * DIN];       // softplus(dt@W + b)
__device__ float g_yg[(size_t)ROWS * DIN];          // gated scan out (tf32-rounded)
__device__ float g_w1[(size_t)DM * 2 * DIN];        // in_proj_w  tf32-rounded
__device__ float g_w2[(size_t)DIN * DM];            // out_proj_w tf32-rounded

// ---------------------------------------------------------------------------
// helpers
// ---------------------------------------------------------------------------
__device__ __forceinline__ float round_tf32(float v) {
    uint32_t r;
    asm("cvt.rna.tf32.f32 %0, %1;" : "=r"(r) : "f"(v));
    return __uint_as_float(r);
}
__device__ __forceinline__ void cpa16(float* smem_dst, const float* g) {
    uint32_t s;
    asm("{ .reg .u64 t; cvta.to.shared.u64 t, %1; cvt.u32.u64 %0, t; }"
        : "=r"(s) : "l"(smem_dst));
    asm volatile("cp.async.cg.shared.global [%0], [%1], 16;" :: "r"(s), "l"(g));
}
__device__ __forceinline__ void mma_tf32(float* c, const uint32_t* a,
                                         const uint32_t* b) {
    asm volatile(
        "mma.sync.aligned.m16n8k8.row.col.f32.tf32.tf32.f32 "
        "{%0,%1,%2,%3}, {%4,%5,%6,%7}, {%8,%9}, {%0,%1,%2,%3};"
        : "+f"(c[0]), "+f"(c[1]), "+f"(c[2]), "+f"(c[3])
        : "r"(a[0]), "r"(a[1]), "r"(a[2]), "r"(a[3]), "r"(b[0]), "r"(b[1]));
}

// ---------------------------------------------------------------------------
// tf32 tensor-core GEMM: C[M,N] = A[M,K] @ B[K,N]   (both row-major fp32,
// values pre-rounded to tf32). CTA tile 128x128, BK=32, double-buffered
// cp.async. 8 warps in 2(m) x 4(n); warp tile 64x32; m16n8k8 HMMA.
// ---------------------------------------------------------------------------
#define AS_STRIDE 36
#define BS_STRIDE 132
#define AS_FLOATS (128 * AS_STRIDE)             // 4608
#define BS_FLOATS (32 * BS_STRIDE)              // 4224
#define STAGE_FLOATS (AS_FLOATS + BS_FLOATS)    // 8832
#define GEMM_SMEM_BYTES (2 * STAGE_FLOATS * 4)  // 70656

template <bool RESID>
__global__ void __launch_bounds__(256, 1)
mma_gemm(const float* __restrict__ A, const float* __restrict__ B,
         float* __restrict__ C, const float* __restrict__ resid,
         int K, int N, int ldc) {
    extern __shared__ float sm[];
    const int tid = threadIdx.x;
    const int lane = tid & 31, wid = tid >> 5;
    const int wm = (wid & 1) * 64;        // warp m offset in tile
    const int wn = (wid >> 1) * 32;       // warp n offset in tile
    const int m0 = blockIdx.y * 128;
    const int n0 = blockIdx.x * 128;
    const int g = lane >> 2, tk = lane & 3;

    float acc[4][4][4];
#pragma unroll
    for (int i = 0; i < 4; i++)
#pragma unroll
        for (int j = 0; j < 4; j++)
#pragma unroll
            for (int l = 0; l < 4; l++) acc[i][j][l] = 0.f;

    const int nCh = K >> 5;

    // ---- stage loader ----
    auto load_stage = [&](int ch, int s) {
        float* As = sm + s * STAGE_FLOATS;
        float* Bs = As + AS_FLOATS;
        const int k0 = ch * 32;
#pragma unroll
        for (int i = 0; i < 4; i++) {
            const int t = tid + i * 256;
            const int row = t >> 3, kq = (t & 7) * 4;
            cpa16(&As[row * AS_STRIDE + kq], &A[(size_t)(m0 + row) * K + k0 + kq]);
        }
#pragma unroll
        for (int i = 0; i < 4; i++) {
            const int t = tid + i * 256;
            const int kr = t >> 5, nq = (t & 31) * 4;
            cpa16(&Bs[kr * BS_STRIDE + nq], &B[(size_t)(k0 + kr) * N + n0 + nq]);
        }
        asm volatile("cp.async.commit_group;");
    };

    load_stage(0, 0);

#pragma unroll 1
    for (int ch = 0; ch < nCh; ch++) {
        const int s = ch & 1;
        if (ch + 1 < nCh) {
            load_stage(ch + 1, s ^ 1);
            asm volatile("cp.async.wait_group 1;" ::: "memory");
        } else {
            asm volatile("cp.async.wait_group 0;" ::: "memory");
        }
        __syncthreads();

        const uint32_t* Asu = reinterpret_cast<const uint32_t*>(sm + s * STAGE_FLOATS);
        const uint32_t* Bsu = Asu + AS_FLOATS;
#pragma unroll
        for (int kk = 0; kk < 32; kk += 8) {
            uint32_t bfr[4][2];
#pragma unroll
            for (int nt = 0; nt < 4; nt++) {
                const int col = wn + nt * 8 + g;
                bfr[nt][0] = Bsu[(kk + tk) * BS_STRIDE + col];
                bfr[nt][1] = Bsu[(kk + tk + 4) * BS_STRIDE + col];
            }
            uint32_t afr[4][4];
#pragma unroll
            for (int mt = 0; mt < 4; mt++) {
                const int base = (wm + mt * 16 + g) * AS_STRIDE + kk + tk;
                afr[mt][0] = Asu[base];
                afr[mt][1] = Asu[base + 8 * AS_STRIDE];
                afr[mt][2] = Asu[base + 4];
                afr[mt][3] = Asu[base + 8 * AS_STRIDE + 4];
            }
#pragma unroll
            for (int mt = 0; mt < 4; mt++)
#pragma unroll
                for (int nt = 0; nt < 4; nt++)
                    mma_tf32(acc[mt][nt], afr[mt], bfr[nt]);
        }
        __syncthreads();
    }

    // ---- epilogue: direct fragment stores (float2, 32B sectors) ----
#pragma unroll
    for (int mt = 0; mt < 4; mt++) {
        const int row = m0 + wm + mt * 16 + g;
#pragma unroll
        for (int nt = 0; nt < 4; nt++) {
            const int col = n0 + wn + nt * 8 + tk * 2;
            float2 v0 = make_float2(acc[mt][nt][0], acc[mt][nt][1]);
            float2 v1 = make_float2(acc[mt][nt][2], acc[mt][nt][3]);
            const size_t o0 = (size_t)row * ldc + col;
            const size_t o1 = (size_t)(row + 8) * ldc + col;
            if (RESID) {
                const float2 r0 = *reinterpret_cast<const float2*>(&resid[o0]);
                const float2 r1 = *reinterpret_cast<const float2*>(&resid[o1]);
                v0.x += r0.x; v0.y += r0.y;
                v1.x += r1.x; v1.y += r1.y;
            }
            *reinterpret_cast<float2*>(&C[o0]) = v0;
            *reinterpret_cast<float2*>(&C[o1]) = v1;
        }
    }
}

// ---------------------------------------------------------------------------
// LayerNorm -> tf32-rounded fp32
// ---------------------------------------------------------------------------
__global__ void ln_kernel(const float* __restrict__ x,
                          const float* __restrict__ g,
                          const float* __restrict__ b) {
    const int row = blockIdx.x;
    const int tid = threadIdx.x;
    const float4 v = reinterpret_cast<const float4*>(x + (size_t)row * DM)[tid];
    float s = v.x + v.y + v.z + v.w;
    float q = v.x * v.x + v.y * v.y + v.z * v.z + v.w * v.w;
#pragma unroll
    for (int o = 16; o > 0; o >>= 1) {
        s += __shfl_xor_sync(0xffffffffu, s, o);
        q += __shfl_xor_sync(0xffffffffu, q, o);
    }
    __shared__ float rs[8], rq[8];
    if ((tid & 31) == 0) { rs[tid >> 5] = s; rq[tid >> 5] = q; }
    __syncthreads();
    s = 0.f; q = 0.f;
#pragma unroll
    for (int i = 0; i < 8; i++) { s += rs[i]; q += rq[i]; }
    const float mean = s * (1.f / DM);
    const float var  = q * (1.f / DM) - mean * mean;
    const float rstd = rsqrtf(var + 1e-5f);
    const float4 gv = reinterpret_cast<const float4*>(g)[tid];
    const float4 bv = reinterpret_cast<const float4*>(b)[tid];
    float4 o;
    o.x = round_tf32((v.x - mean) * rstd * gv.x + bv.x);
    o.y = round_tf32((v.y - mean) * rstd * gv.y + bv.y);
    o.z = round_tf32((v.z - mean) * rstd * gv.z + bv.z);
    o.w = round_tf32((v.w - mean) * rstd * gv.w + bv.w);
    reinterpret_cast<float4*>(g_xn + (size_t)row * DM)[tid] = o;
}

// ---------------------------------------------------------------------------
// Elementwise tf32 rounding (weight prep)
// ---------------------------------------------------------------------------
__global__ void round_kernel(const float* __restrict__ in, float* __restrict__ out,
                             int n4) {
    const int i = blockIdx.x * 256 + threadIdx.x;
    if (i >= n4) return;
    float4 v = reinterpret_cast<const float4*>(in)[i];
    v.x = round_tf32(v.x); v.y = round_tf32(v.y);
    v.z = round_tf32(v.z); v.w = round_tf32(v.w);
    reinterpret_cast<float4*>(out)[i] = v;
}

// ---------------------------------------------------------------------------
// SIMT fp32 GEMM (f32x2) for small projections
// ---------------------------------------------------------------------------
__device__ __forceinline__ unsigned long long pack_dup(float a) {
    unsigned long long r;
    asm("mov.b64 %0, {%1, %1};" : "=l"(r) : "f"(a));
    return r;
}
__device__ __forceinline__ void ffma2(unsigned long long& d,
                                      unsigned long long a,
                                      unsigned long long b) {
    asm("fma.rn.f32x2 %0, %1, %2, %0;" : "+l"(d) : "l"(a), "l"(b));
}

template <int EPI, bool GUARD_N, bool SPLITK>
__global__ void __launch_bounds__(256, 2)
sgemm_kernel(const float* __restrict__ A, const float* __restrict__ B,
             float* __restrict__ C, int M, int N, int K,
             int lda, int ldb, int ldc, const float* __restrict__ aux) {
    __shared__ float As[8][132];
    __shared__ float Bs[8][132];
    const int tid = threadIdx.x;
    const int tx = tid & 15, ty = tid >> 4;
    const int rowBase = blockIdx.y * 128;
    const int colBase = blockIdx.x * 128;
    const int ar = tid >> 1, ak = (tid & 1) * 4;
    const int br = tid >> 5, bc = (tid & 31) * 4;

    int k0 = 0, kEnd = K;
    if (SPLITK) {
        const int chunk = K / gridDim.z;
        k0 = blockIdx.z * chunk;
        kEnd = k0 + chunk;
    }
    union AccU { float f[8][8]; unsigned long long u[8][4]; } acc;
#pragma unroll
    for (int i = 0; i < 8; i++)
#pragma unroll
        for (int j = 0; j < 4; j++) acc.u[i][j] = 0ULL;

    for (; k0 < kEnd; k0 += 8) {
        const float4 av = *reinterpret_cast<const float4*>(
            &A[(size_t)(rowBase + ar) * lda + k0 + ak]);
        As[ak + 0][ar] = av.x; As[ak + 1][ar] = av.y;
        As[ak + 2][ar] = av.z; As[ak + 3][ar] = av.w;
        float4 bv = make_float4(0.f, 0.f, 0.f, 0.f);
        if (!GUARD_N || (colBase + bc) < N)
            bv = *reinterpret_cast<const float4*>(
                &B[(size_t)(k0 + br) * ldb + colBase + bc]);
        *reinterpret_cast<float4*>(&Bs[br][bc]) = bv;
        __syncthreads();
#pragma unroll
        for (int kk = 0; kk < 8; kk++) {
            float afr[8];
            union { float f[8]; unsigned long long u[4]; } bfr;
            *reinterpret_cast<float4*>(&afr[0]) =
                *reinterpret_cast<const float4*>(&As[kk][ty * 8]);
            *reinterpret_cast<float4*>(&afr[4]) =
                *reinterpret_cast<const float4*>(&As[kk][ty * 8 + 4]);
            *reinterpret_cast<float4*>(&bfr.f[0]) =
                *reinterpret_cast<const float4*>(&Bs[kk][tx * 8]);
            *reinterpret_cast<float4*>(&bfr.f[4]) =
                *reinterpret_cast<const float4*>(&Bs[kk][tx * 8 + 4]);
#pragma unroll
            for (int i = 0; i < 8; i++) {
                const unsigned long long ap = pack_dup(afr[i]);
#pragma unroll
                for (int j = 0; j < 4; j++) ffma2(acc.u[i][j], ap, bfr.u[j]);
            }
        }
        __syncthreads();
    }
#pragma unroll
    for (int i = 0; i < 8; i++) {
        const int row = rowBase + ty * 8 + i;
#pragma unroll
        for (int j = 0; j < 8; j++) {
            const int col = colBase + tx * 8 + j;
            if (GUARD_N && col >= N) continue;
            float v = acc.f[i][j];
            if (SPLITK) {
                atomicAdd(&C[(size_t)row * ldc + col], v);
            } else {
                if (EPI == 1) {
                    v += aux[col];
                    v = (v > 20.f) ? v : log1pf(__expf(v));
                }
                C[(size_t)row * ldc + col] = v;
            }
        }
    }
}

// ---------------------------------------------------------------------------
// Depthwise causal conv (k=4) + bias + SiLU
// ---------------------------------------------------------------------------
__global__ void conv_silu_kernel(const float* __restrict__ cw,
                                 const float* __restrict__ cb) {
    const int idx = blockIdx.x * blockDim.x + threadIdx.x;
    const int d = idx & (DIN - 1);
    const int row = idx >> 11;
    const int l = row & (LL - 1);
    const int b = row >> 11;
    const float* base = g_xz + (size_t)(b * LL) * (2 * DIN) + d;
    float acc = cb[d];
    if (l >= 3) {
        acc += cw[d * 4 + 0] * base[(size_t)(l - 3) * (2 * DIN)]
             + cw[d * 4 + 1] * base[(size_t)(l - 2) * (2 * DIN)]
             + cw[d * 4 + 2] * base[(size_t)(l - 1) * (2 * DIN)]
             + cw[d * 4 + 3] * base[(size_t)(l    ) * (2 * DIN)];
    } else {
#pragma unroll
        for (int j = 0; j < 4; j++) {
            const int ll2 = l + j - 3;
            if (ll2 >= 0) acc += cw[d * 4 + j] * base[(size_t)ll2 * (2 * DIN)];
        }
    }
    acc = acc / (1.f + __expf(-acc));
    g_u[(size_t)row * DIN + d] = acc;
}

__global__ void zero_kernel(float* __restrict__ p, int n) {
    const int i = blockIdx.x * blockDim.x + threadIdx.x;
    if (i < n) p[i] = 0.f;
}

// ---------------------------------------------------------------------------
// Chunked parallel selective scan.
// Block = 1024 threads = 2 channels x 32 chunks of 64 steps.
// Warp w = chunk w; lane = (half, n): half = channel within block, n = state.
// Pass 1: per-chunk (P = prod a, S = local h from 0).
// Combine: warp 0 serial over 32 chunks in smem -> h_init per chunk.
// Pass 2: replay chunk from h_init; y = sum_n h*C; gate with silu(z).
// ---------------------------------------------------------------------------
__global__ void __launch_bounds__(1024, 1)
scan_kernel(const float* __restrict__ A_log, const float* __restrict__ Dv) {
    __shared__ float sP[NCHUNK][32];
    __shared__ float sS[NCHUNK][32];
    __shared__ float sH[NCHUNK][32];
    const int tid = threadIdx.x;
    const int wid = tid >> 5;           // chunk index
    const int lane = tid & 31;
    const int half = lane >> 4;         // channel within block
    const int n = lane & 15;
    const int ch = blockIdx.x * 2 + half;   // both halves share batch b
    const int b = ch >> 11;
    const int d = ch & (DIN - 1);

    const float An = -__expf(A_log[d * NST + n]);
    const float Dd = Dv[d];
    const size_t rowStart = (size_t)b * LL + wid * CHUNK;

    // ---- pass 1: chunk-local (P, S) ----
    float P = 1.f, S = 0.f;
#pragma unroll 4
    for (int j = 0; j < CHUNK; j++) {
        const size_t row = rowStart + j;
        const float dv = g_delta[row * DIN + d];
        const float uv = g_u[row * DIN + d];
        const float Bn = g_dbc[row * DBC_COLS + DTR + n];
        const float a = __expf(dv * An);
        S = fmaf(a, S, dv * Bn * uv);
        P *= a;
    }
    sP[wid][lane] = P;
    sS[wid][lane] = S;
    __syncthreads();

    // ---- combine: serial over chunks (warp 0) ----
    if (wid == 0) {
        float run = 0.f;
#pragma unroll
        for (int c = 0; c < NCHUNK; c++) {
            sH[c][lane] = run;
            run = fmaf(sP[c][lane], run, sS[c][lane]);
        }
    }
    __syncthreads();

    // ---- pass 2: replay with correct initial state ----
    float h = sH[wid][lane];
#pragma unroll 4
    for (int j = 0; j < CHUNK; j++) {
        const size_t row = rowStart + j;
        const float dv = g_delta[row * DIN + d];
        const float uv = g_u[row * DIN + d];
        const float Bn = g_dbc[row * DBC_COLS + DTR + n];
        const float Cn = g_dbc[row * DBC_COLS + DTR + NST + n];
        const float a = __expf(dv * An);
        h = fmaf(a, h, dv * Bn * uv);
        float p = h * Cn;
        p += __shfl_xor_sync(0xffffffffu, p, 8);
        p += __shfl_xor_sync(0xffffffffu, p, 4);
        p += __shfl_xor_sync(0xffffffffu, p, 2);
        p += __shfl_xor_sync(0xffffffffu, p, 1);
        if (n == 0) {
            const float zv = g_xz[row * (2 * DIN) + DIN + d];
            const float yv = fmaf(uv, Dd, p);
            const float sz = zv / (1.f + __expf(-zv));
            g_yg[row * DIN + d] = round_tf32(yv * sz);
        }
    }
}

// ---------------------------------------------------------------------------
// Launch
// ---------------------------------------------------------------------------
extern "C" void kernel_launch(void* const* d_in, const int* in_sizes, int n_in,
                              void* d_out, int out_size) {
    (void)in_sizes; (void)n_in; (void)out_size;
    const float* x         = (const float*)d_in[0];
    const float* in_proj_w = (const float*)d_in[1];
    const float* conv_w    = (const float*)d_in[2];
    const float* conv_b    = (const float*)d_in[3];
    const float* x_proj_w  = (const float*)d_in[4];
    const float* dt_proj_w = (const float*)d_in[5];
    const float* dt_proj_b = (const float*)d_in[6];
    const float* A_log     = (const float*)d_in[7];
    const float* Dvec      = (const float*)d_in[8];
    const float* out_proj_w= (const float*)d_in[9];
    const float* ln_g      = (const float*)d_in[10];
    const float* ln_b      = (const float*)d_in[11];
    float* out = (float*)d_out;

    float *xn, *xz, *u, *dbc, *delta, *yg, *w1, *w2;
    cudaGetSymbolAddress((void**)&xn,    g_xn);
    cudaGetSymbolAddress((void**)&xz,    g_xz);
    cudaGetSymbolAddress((void**)&u,     g_u);
    cudaGetSymbolAddress((void**)&dbc,   g_dbc);
    cudaGetSymbolAddress((void**)&delta, g_delta);
    cudaGetSymbolAddress((void**)&yg,    g_yg);
    cudaGetSymbolAddress((void**)&w1,    g_w1);
    cudaGetSymbolAddress((void**)&w2,    g_w2);

    cudaFuncSetAttribute(mma_gemm<false>,
                         cudaFuncAttributeMaxDynamicSharedMemorySize, GEMM_SMEM_BYTES);
    cudaFuncSetAttribute(mma_gemm<true>,
                         cudaFuncAttributeMaxDynamicSharedMemorySize, GEMM_SMEM_BYTES);

    // weight prep: tf32-round
    round_kernel<<<(DM * 2 * DIN / 4 + 255) / 256, 256>>>(in_proj_w, w1, DM * 2 * DIN / 4);
    round_kernel<<<(DIN * DM / 4 + 255) / 256, 256>>>(out_proj_w, w2, DIN * DM / 4);

    // 1. LayerNorm -> tf32-rounded
    ln_kernel<<<ROWS, 256>>>(x, ln_g, ln_b);

    // 2. in_proj (HMMA tf32): xz[4096,4096] = xn[4096,1024] @ W1[1024,4096]
    mma_gemm<false><<<dim3((2 * DIN) / 128, ROWS / 128), 256, GEMM_SMEM_BYTES>>>(
        xn, w1, xz, nullptr, DM, 2 * DIN, 2 * DIN);

    // 3. conv + SiLU -> u
    conv_silu_kernel<<<(ROWS * DIN) / 256, 256>>>(conv_w, conv_b);

    // 4. x_proj (SIMT split-K)
    zero_kernel<<<(ROWS * DBC_COLS) / 256, 256>>>(dbc, ROWS * DBC_COLS);
    sgemm_kernel<0, true, true><<<dim3(1, 32, 8), 256>>>(
        u, x_proj_w, dbc, ROWS, DBC_COLS, DIN, DIN, DBC_COLS, DBC_COLS, nullptr);

    // 5. dt_proj + softplus (SIMT)
    sgemm_kernel<1, false, false><<<dim3(16, 32), 256>>>(
        dbc, dt_proj_w, delta, ROWS, DIN, DTR, DBC_COLS, DIN, DIN, dt_proj_b);

    // 6. chunked parallel scan -> yg (tf32-rounded)
    scan_kernel<<<(BB * DIN) / 2, 1024>>>(A_log, Dvec);

    // 7. out_proj (HMMA tf32) + residual: out = x + yg[4096,2048] @ W2[2048,1024]
    mma_gemm<true><<<dim3(DM / 128, ROWS / 128), 256, GEMM_SMEM_BYTES>>>(
        yg, w2, out, x, DIN, DM, DM);
}

// round 8
// speedup vs baseline: 2.9565x; 1.2069x over previous
#include <cuda_runtime.h>
#include <cuda_fp16.h>
#include <cstdint>
#include <cstdio>

// Problem constants
#define BB   2
#define LL   2048
#define DM   1024
#define DIN  2048
#define NST  16
#define DTR  64
#define ROWS (BB * LL)   // 4096
#define DBC_COLS 96
#define CHUNK  64
#define NCHUNK 32        // LL / CHUNK

// ---------------------------------------------------------------------------
// Scratch (static device globals — no allocation allowed)
// ---------------------------------------------------------------------------
__device__ __half g_xnh[(size_t)ROWS * DM];         // LN out, fp16
__device__ float  g_xz[(size_t)ROWS * 2 * DIN];     // in_proj out (u | z)
__device__ float  g_u[(size_t)ROWS * DIN];          // silu(conv(u))
__device__ float  g_dbc[(size_t)ROWS * DBC_COLS];   // dt | B | C
__device__ float  g_delta[(size_t)ROWS * DIN];      // softplus(dt@W + b)
__device__ __half g_ygh[(size_t)ROWS * DIN];        // gated scan out, fp16
__device__ __half g_w1t[(size_t)(2 * DIN) * DM];    // in_proj_w^T  [4096][1024]
__device__ __half g_w2t[(size_t)DM * DIN];          // out_proj_w^T [1024][2048]

// ---------------------------------------------------------------------------
// helpers
// ---------------------------------------------------------------------------
__device__ __forceinline__ void cpa16(void* smem_dst, const void* g) {
    uint32_t s;
    asm("{ .reg .u64 t; cvta.to.shared.u64 t, %1; cvt.u32.u64 %0, t; }"
        : "=r"(s) : "l"(smem_dst));
    asm volatile("cp.async.cg.shared.global [%0], [%1], 16;" :: "r"(s), "l"(g));
}
__device__ __forceinline__ void mma_f16(float* c, const uint32_t* a,
                                        const uint32_t* b) {
    asm volatile(
        "mma.sync.aligned.m16n8k16.row.col.f32.f16.f16.f32 "
        "{%0,%1,%2,%3}, {%4,%5,%6,%7}, {%8,%9}, {%0,%1,%2,%3};"
        : "+f"(c[0]), "+f"(c[1]), "+f"(c[2]), "+f"(c[3])
        : "r"(a[0]), "r"(a[1]), "r"(a[2]), "r"(a[3]), "r"(b[0]), "r"(b[1]));
}

// ---------------------------------------------------------------------------
// fp16 tensor-core GEMM: C[M,N] = A[M,K] @ Bt[N,K]^T
// A: [M][K] half row-major.  Bt: [N][K] half row-major (pre-transposed).
// CTA tile 128x128, BK=32, 3-stage cp.async pipeline.
// 8 warps 2(m) x 4(n); warp tile 64x32; m16n8k16 HMMA, fp32 accum.
// Smem rows padded to 40 halves (80 B): the (g, 2tk) access pattern covers
// all 32 banks exactly once -> conflict-free.
// ---------------------------------------------------------------------------
#define HPAD 40
#define TILE_HALVES (128 * HPAD)                    // per operand per stage
#define STAGE_HALVES (2 * TILE_HALVES)              // A + B
#define NSTAGE 3
#define GEMM_SMEM_BYTES (NSTAGE * STAGE_HALVES * 2) // 61440

template <bool RESID>
__global__ void __launch_bounds__(256, 1)
mma_gemm(const __half* __restrict__ A, const __half* __restrict__ Bt,
         float* __restrict__ C, const float* __restrict__ resid,
         int K, int ldc) {
    extern __shared__ __half smh[];
    const int tid = threadIdx.x;
    const int lane = tid & 31, wid = tid >> 5;
    const int wm = (wid & 1) * 64;
    const int wn = (wid >> 1) * 32;
    const int m0 = blockIdx.y * 128;
    const int n0 = blockIdx.x * 128;
    const int g = lane >> 2, tk = lane & 3;

    float acc[4][4][4];
#pragma unroll
    for (int i = 0; i < 4; i++)
#pragma unroll
        for (int j = 0; j < 4; j++)
#pragma unroll
            for (int l = 0; l < 4; l++) acc[i][j][l] = 0.f;

    const int nCh = K >> 5;

    auto load_stage = [&](int ch, int s) {
        __half* As = smh + s * STAGE_HALVES;
        __half* Bs = As + TILE_HALVES;
        const int k0 = ch * 32;
#pragma unroll
        for (int i = 0; i < 2; i++) {
            const int t = tid + i * 256;           // 0..511
            const int row = t >> 2, seg = (t & 3) * 8;
            cpa16(&As[row * HPAD + seg], &A[(size_t)(m0 + row) * K + k0 + seg]);
        }
#pragma unroll
        for (int i = 0; i < 2; i++) {
            const int t = tid + i * 256;
            const int row = t >> 2, seg = (t & 3) * 8;
            cpa16(&Bs[row * HPAD + seg], &Bt[(size_t)(n0 + row) * K + k0 + seg]);
        }
        asm volatile("cp.async.commit_group;");
    };

    load_stage(0, 0);
    if (nCh > 1) load_stage(1, 1);
    else asm volatile("cp.async.commit_group;");

#pragma unroll 1
    for (int ch = 0; ch < nCh; ch++) {
        __syncthreads();   // all warps done reading the stage we now overwrite
        if (ch + 2 < nCh) load_stage(ch + 2, (ch + 2) % NSTAGE);
        else asm volatile("cp.async.commit_group;");
        asm volatile("cp.async.wait_group 2;" ::: "memory");
        __syncthreads();

        const __half* As = smh + (ch % NSTAGE) * STAGE_HALVES;
        const __half* Bs = As + TILE_HALVES;
#pragma unroll
        for (int s16 = 0; s16 < 2; s16++) {
            const int kb = s16 * 16;
            uint32_t bfr[4][2];
#pragma unroll
            for (int nt = 0; nt < 4; nt++) {
                const int col = wn + nt * 8 + g;
                bfr[nt][0] = *reinterpret_cast<const uint32_t*>(
                    &Bs[col * HPAD + kb + 2 * tk]);
                bfr[nt][1] = *reinterpret_cast<const uint32_t*>(
                    &Bs[col * HPAD + kb + 2 * tk + 8]);
            }
            uint32_t afr[4][4];
#pragma unroll
            for (int mt = 0; mt < 4; mt++) {
                const int row = wm + mt * 16 + g;
                afr[mt][0] = *reinterpret_cast<const uint32_t*>(
                    &As[row * HPAD + kb + 2 * tk]);
                afr[mt][1] = *reinterpret_cast<const uint32_t*>(
                    &As[(row + 8) * HPAD + kb + 2 * tk]);
                afr[mt][2] = *reinterpret_cast<const uint32_t*>(
                    &As[row * HPAD + kb + 2 * tk + 8]);
                afr[mt][3] = *reinterpret_cast<const uint32_t*>(
                    &As[(row + 8) * HPAD + kb + 2 * tk + 8]);
            }
#pragma unroll
            for (int mt = 0; mt < 4; mt++)
#pragma unroll
                for (int nt = 0; nt < 4; nt++)
                    mma_f16(acc[mt][nt], afr[mt], bfr[nt]);
        }
    }

    // ---- epilogue: fragment stores (float2) ----
#pragma unroll
    for (int mt = 0; mt < 4; mt++) {
        const int row = m0 + wm + mt * 16 + g;
#pragma unroll
        for (int nt = 0; nt < 4; nt++) {
            const int col = n0 + wn + nt * 8 + tk * 2;
            float2 v0 = make_float2(acc[mt][nt][0], acc[mt][nt][1]);
            float2 v1 = make_float2(acc[mt][nt][2], acc[mt][nt][3]);
            const size_t o0 = (size_t)row * ldc + col;
            const size_t o1 = (size_t)(row + 8) * ldc + col;
            if (RESID) {
                const float2 r0 = *reinterpret_cast<const float2*>(&resid[o0]);
                const float2 r1 = *reinterpret_cast<const float2*>(&resid[o1]);
                v0.x += r0.x; v0.y += r0.y;
                v1.x += r1.x; v1.y += r1.y;
            }
            *reinterpret_cast<float2*>(&C[o0]) = v0;
            *reinterpret_cast<float2*>(&C[o1]) = v1;
        }
    }
}

// ---------------------------------------------------------------------------
// LayerNorm -> fp16
// ---------------------------------------------------------------------------
__global__ void ln_kernel(const float* __restrict__ x,
                          const float* __restrict__ g,
                          const float* __restrict__ b) {
    const int row = blockIdx.x;
    const int tid = threadIdx.x;
    const float4 v = reinterpret_cast<const float4*>(x + (size_t)row * DM)[tid];
    float s = v.x + v.y + v.z + v.w;
    float q = v.x * v.x + v.y * v.y + v.z * v.z + v.w * v.w;
#pragma unroll
    for (int o = 16; o > 0; o >>= 1) {
        s += __shfl_xor_sync(0xffffffffu, s, o);
        q += __shfl_xor_sync(0xffffffffu, q, o);
    }
    __shared__ float rs[8], rq[8];
    if ((tid & 31) == 0) { rs[tid >> 5] = s; rq[tid >> 5] = q; }
    __syncthreads();
    s = 0.f; q = 0.f;
#pragma unroll
    for (int i = 0; i < 8; i++) { s += rs[i]; q += rq[i]; }
    const float mean = s * (1.f / DM);
    const float var  = q * (1.f / DM) - mean * mean;
    const float rstd = rsqrtf(var + 1e-5f);
    const float4 gv = reinterpret_cast<const float4*>(g)[tid];
    const float4 bv = reinterpret_cast<const float4*>(b)[tid];
    const __half2 h01 = __floats2half2_rn((v.x - mean) * rstd * gv.x + bv.x,
                                          (v.y - mean) * rstd * gv.y + bv.y);
    const __half2 h23 = __floats2half2_rn((v.z - mean) * rstd * gv.z + bv.z,
                                          (v.w - mean) * rstd * gv.w + bv.w);
    uint2 pk;
    pk.x = *reinterpret_cast<const uint32_t*>(&h01);
    pk.y = *reinterpret_cast<const uint32_t*>(&h23);
    *reinterpret_cast<uint2*>(g_xnh + (size_t)row * DM + tid * 4) = pk;
}

// ---------------------------------------------------------------------------
// Transpose + fp16 convert: W[K][N] fp32 -> Wt[N][K] half
// ---------------------------------------------------------------------------
__global__ void transconv_kernel(const float* __restrict__ W,
                                 __half* __restrict__ T, int K, int N) {
    __shared__ float t[32][33];
    const int n0 = blockIdx.x * 32, k0 = blockIdx.y * 32;
    const int x = threadIdx.x, y = threadIdx.y;  // 32 x 8
#pragma unroll
    for (int j = 0; j < 32; j += 8)
        t[y + j][x] = W[(size_t)(k0 + y + j) * N + n0 + x];
    __syncthreads();
#pragma unroll
    for (int j = 0; j < 32; j += 8)
        T[(size_t)(n0 + y + j) * K + k0 + x] = __float2half_rn(t[x][y + j]);
}

// ---------------------------------------------------------------------------
// SIMT fp32 GEMM (f32x2) for small projections
// ---------------------------------------------------------------------------
__device__ __forceinline__ unsigned long long pack_dup(float a) {
    unsigned long long r;
    asm("mov.b64 %0, {%1, %1};" : "=l"(r) : "f"(a));
    return r;
}
__device__ __forceinline__ void ffma2(unsigned long long& d,
                                      unsigned long long a,
                                      unsigned long long b) {
    asm("fma.rn.f32x2 %0, %1, %2, %0;" : "+l"(d) : "l"(a), "l"(b));
}

template <int EPI, bool GUARD_N, bool SPLITK>
__global__ void __launch_bounds__(256, 2)
sgemm_kernel(const float* __restrict__ A, const float* __restrict__ B,
             float* __restrict__ C, int M, int N, int K,
             int lda, int ldb, int ldc, const float* __restrict__ aux) {
    __shared__ float As[8][132];
    __shared__ float Bs[8][132];
    const int tid = threadIdx.x;
    const int tx = tid & 15, ty = tid >> 4;
    const int rowBase = blockIdx.y * 128;
    const int colBase = blockIdx.x * 128;
    const int ar = tid >> 1, ak = (tid & 1) * 4;
    const int br = tid >> 5, bc = (tid & 31) * 4;

    int k0 = 0, kEnd = K;
    if (SPLITK) {
        const int chunk = K / gridDim.z;
        k0 = blockIdx.z * chunk;
        kEnd = k0 + chunk;
    }
    union AccU { float f[8][8]; unsigned long long u[8][4]; } acc;
#pragma unroll
    for (int i = 0; i < 8; i++)
#pragma unroll
        for (int j = 0; j < 4; j++) acc.u[i][j] = 0ULL;

    for (; k0 < kEnd; k0 += 8) {
        const float4 av = *reinterpret_cast<const float4*>(
            &A[(size_t)(rowBase + ar) * lda + k0 + ak]);
        As[ak + 0][ar] = av.x; As[ak + 1][ar] = av.y;
        As[ak + 2][ar] = av.z; As[ak + 3][ar] = av.w;
        float4 bv = make_float4(0.f, 0.f, 0.f, 0.f);
        if (!GUARD_N || (colBase + bc) < N)
            bv = *reinterpret_cast<const float4*>(
                &B[(size_t)(k0 + br) * ldb + colBase + bc]);
        *reinterpret_cast<float4*>(&Bs[br][bc]) = bv;
        __syncthreads();
#pragma unroll
        for (int kk = 0; kk < 8; kk++) {
            float afr[8];
            union { float f[8]; unsigned long long u[4]; } bfr;
            *reinterpret_cast<float4*>(&afr[0]) =
                *reinterpret_cast<const float4*>(&As[kk][ty * 8]);
            *reinterpret_cast<float4*>(&afr[4]) =
                *reinterpret_cast<const float4*>(&As[kk][ty * 8 + 4]);
            *reinterpret_cast<float4*>(&bfr.f[0]) =
                *reinterpret_cast<const float4*>(&Bs[kk][tx * 8]);
            *reinterpret_cast<float4*>(&bfr.f[4]) =
                *reinterpret_cast<const float4*>(&Bs[kk][tx * 8 + 4]);
#pragma unroll
            for (int i = 0; i < 8; i++) {
                const unsigned long long ap = pack_dup(afr[i]);
#pragma unroll
                for (int j = 0; j < 4; j++) ffma2(acc.u[i][j], ap, bfr.u[j]);
            }
        }
        __syncthreads();
    }
#pragma unroll
    for (int i = 0; i < 8; i++) {
        const int row = rowBase + ty * 8 + i;
#pragma unroll
        for (int j = 0; j < 8; j++) {
            const int col = colBase + tx * 8 + j;
            if (GUARD_N && col >= N) continue;
            float v = acc.f[i][j];
            if (SPLITK) {
                atomicAdd(&C[(size_t)row * ldc + col], v);
            } else {
                if (EPI == 1) {
                    v += aux[col];
                    v = (v > 20.f) ? v : log1pf(__expf(v));
                }
                C[(size_t)row * ldc + col] = v;
            }
        }
    }
}

// ---------------------------------------------------------------------------
// Depthwise causal conv (k=4) + bias + SiLU
// ---------------------------------------------------------------------------
__global__ void conv_silu_kernel(const float* __restrict__ cw,
                                 const float* __restrict__ cb) {
    const int idx = blockIdx.x * blockDim.x + threadIdx.x;
    const int d = idx & (DIN - 1);
    const int row = idx >> 11;
    const int l = row & (LL - 1);
    const int b = row >> 11;
    const float* base = g_xz + (size_t)(b * LL) * (2 * DIN) + d;
    float acc = cb[d];
    if (l >= 3) {
        acc += cw[d * 4 + 0] * base[(size_t)(l - 3) * (2 * DIN)]
             + cw[d * 4 + 1] * base[(size_t)(l - 2) * (2 * DIN)]
             + cw[d * 4 + 2] * base[(size_t)(l - 1) * (2 * DIN)]
             + cw[d * 4 + 3] * base[(size_t)(l    ) * (2 * DIN)];
    } else {
#pragma unroll
        for (int j = 0; j < 4; j++) {
            const int ll2 = l + j - 3;
            if (ll2 >= 0) acc += cw[d * 4 + j] * base[(size_t)ll2 * (2 * DIN)];
        }
    }
    acc = acc / (1.f + __expf(-acc));
    g_u[(size_t)row * DIN + d] = acc;
}

__global__ void zero_kernel(float* __restrict__ p, int n) {
    const int i = blockIdx.x * blockDim.x + threadIdx.x;
    if (i < n) p[i] = 0.f;
}

// ---------------------------------------------------------------------------
// Chunked parallel selective scan (out: fp16 yg for the out_proj GEMM)
// ---------------------------------------------------------------------------
__global__ void __launch_bounds__(1024, 1)
scan_kernel(const float* __restrict__ A_log, const float* __restrict__ Dv) {
    __shared__ float sP[NCHUNK][32];
    __shared__ float sS[NCHUNK][32];
    __shared__ float sH[NCHUNK][32];
    const int tid = threadIdx.x;
    const int wid = tid >> 5;
    const int lane = tid & 31;
    const int half = lane >> 4;
    const int n = lane & 15;
    const int ch = blockIdx.x * 2 + half;
    const int b = ch >> 11;
    const int d = ch & (DIN - 1);

    const float An = -__expf(A_log[d * NST + n]);
    const float Dd = Dv[d];
    const size_t rowStart = (size_t)b * LL + wid * CHUNK;

    float P = 1.f, S = 0.f;
#pragma unroll 8
    for (int j = 0; j < CHUNK; j++) {
        const size_t row = rowStart + j;
        const float dv = g_delta[row * DIN + d];
        const float uv = g_u[row * DIN + d];
        const float Bn = g_dbc[row * DBC_COLS + DTR + n];
        const float a = __expf(dv * An);
        S = fmaf(a, S, dv * Bn * uv);
        P *= a;
    }
    sP[wid][lane] = P;
    sS[wid][lane] = S;
    __syncthreads();

    if (wid == 0) {
        float run = 0.f;
#pragma unroll
        for (int c = 0; c < NCHUNK; c++) {
            sH[c][lane] = run;
            run = fmaf(sP[c][lane], run, sS[c][lane]);
        }
    }
    __syncthreads();

    float h = sH[wid][lane];
#pragma unroll 8
    for (int j = 0; j < CHUNK; j++) {
        const size_t row = rowStart + j;
        const float dv = g_delta[row * DIN + d];
        const float uv = g_u[row * DIN + d];
        const float Bn = g_dbc[row * DBC_COLS + DTR + n];
        const float Cn = g_dbc[row * DBC_COLS + DTR + NST + n];
        const float a = __expf(dv * An);
        h = fmaf(a, h, dv * Bn * uv);
        float p = h * Cn;
        p += __shfl_xor_sync(0xffffffffu, p, 8);
        p += __shfl_xor_sync(0xffffffffu, p, 4);
        p += __shfl_xor_sync(0xffffffffu, p, 2);
        p += __shfl_xor_sync(0xffffffffu, p, 1);
        if (n == 0) {
            const float zv = g_xz[row * (2 * DIN) + DIN + d];
            const float yv = fmaf(uv, Dd, p);
            const float sz = zv / (1.f + __expf(-zv));
            g_ygh[row * DIN + d] = __float2half_rn(yv * sz);
        }
    }
}

// ---------------------------------------------------------------------------
// Launch
// ---------------------------------------------------------------------------
extern "C" void kernel_launch(void* const* d_in, const int* in_sizes, int n_in,
                              void* d_out, int out_size) {
    (void)in_sizes; (void)n_in; (void)out_size;
    const float* x         = (const float*)d_in[0];
    const float* in_proj_w = (const float*)d_in[1];
    const float* conv_w    = (const float*)d_in[2];
    const float* conv_b    = (const float*)d_in[3];
    const float* x_proj_w  = (const float*)d_in[4];
    const float* dt_proj_w = (const float*)d_in[5];
    const float* dt_proj_b = (const float*)d_in[6];
    const float* A_log     = (const float*)d_in[7];
    const float* Dvec      = (const float*)d_in[8];
    const float* out_proj_w= (const float*)d_in[9];
    const float* ln_g      = (const float*)d_in[10];
    const float* ln_b      = (const float*)d_in[11];
    float* out = (float*)d_out;

    float *xz, *u, *dbc, *delta;
    __half *xnh, *ygh, *w1t, *w2t;
    cudaGetSymbolAddress((void**)&xz,    g_xz);
    cudaGetSymbolAddress((void**)&u,     g_u);
    cudaGetSymbolAddress((void**)&dbc,   g_dbc);
    cudaGetSymbolAddress((void**)&delta, g_delta);
    cudaGetSymbolAddress((void**)&xnh,   g_xnh);
    cudaGetSymbolAddress((void**)&ygh,   g_ygh);
    cudaGetSymbolAddress((void**)&w1t,   g_w1t);
    cudaGetSymbolAddress((void**)&w2t,   g_w2t);

    cudaFuncSetAttribute(mma_gemm<false>,
                         cudaFuncAttributeMaxDynamicSharedMemorySize, GEMM_SMEM_BYTES);
    cudaFuncSetAttribute(mma_gemm<true>,
                         cudaFuncAttributeMaxDynamicSharedMemorySize, GEMM_SMEM_BYTES);

    // weight prep: transpose + fp16
    transconv_kernel<<<dim3((2 * DIN) / 32, DM / 32), dim3(32, 8)>>>(
        in_proj_w, w1t, DM, 2 * DIN);
    transconv_kernel<<<dim3(DM / 32, DIN / 32), dim3(32, 8)>>>(
        out_proj_w, w2t, DIN, DM);

    // 1. LayerNorm -> fp16
    ln_kernel<<<ROWS, 256>>>(x, ln_g, ln_b);

    // 2. in_proj (HMMA fp16): xz[4096,4096] = xn @ W1
    mma_gemm<false><<<dim3((2 * DIN) / 128, ROWS / 128), 256, GEMM_SMEM_BYTES>>>(
        xnh, w1t, xz, nullptr, DM, 2 * DIN);

    // 3. conv + SiLU -> u
    conv_silu_kernel<<<(ROWS * DIN) / 256, 256>>>(conv_w, conv_b);

    // 4. x_proj (SIMT split-K)
    zero_kernel<<<(ROWS * DBC_COLS) / 256, 256>>>(dbc, ROWS * DBC_COLS);
    sgemm_kernel<0, true, true><<<dim3(1, 32, 8), 256>>>(
        u, x_proj_w, dbc, ROWS, DBC_COLS, DIN, DIN, DBC_COLS, DBC_COLS, nullptr);

    // 5. dt_proj + softplus (SIMT)
    sgemm_kernel<1, false, false><<<dim3(16, 32), 256>>>(
        dbc, dt_proj_w, delta, ROWS, DIN, DTR, DBC_COLS, DIN, DIN, dt_proj_b);

    // 6. chunked parallel scan -> yg fp16
    scan_kernel<<<(BB * DIN) / 2, 1024>>>(A_log, Dvec);

    // 7. out_proj (HMMA fp16) + residual
    mma_gemm<true><<<dim3(DM / 128, ROWS / 128), 256, GEMM_SMEM_BYTES>>>(
        ygh, w2t, out, x, DIN, DM);
}